// round 17
// baseline (speedup 1.0000x reference)
#include <cuda_runtime.h>
#include <stdint.h>

#define B_  32
#define H_  512
#define W_  512
#define PIX_PER_IMG (H_ * W_)                    // 262144
#define CPB 128                                  // chunks (blocks) per batch
#define GRID_TOTAL (B_ * CPB)                    // 4096 blocks
#define MF4 (PIX_PER_IMG / CPB / 4)              // 512 float4 of mk per block
#define SHIFT_ELEMS 8                            // 8 float4 x-pixels per thread
#define FP_SCALE 1048576.0f                      // 2^20 (exact float scaling)

// Scratch (no allocations allowed) — zero-init; self-reset every launch.
__device__ long long    g_tot[B_ * 3];    // fixed-point (m00,m10,m01) per batch
__device__ int          g_shift[B_ * 2];  // (dx, dy) ints per batch
__device__ unsigned int g_cnt[B_];        // per-batch arrival counters
__device__ unsigned int g_ready[B_];      // per-batch release flags
__device__ unsigned int g_done;           // global completion counter

// ---------------------------------------------------------------------------
// Single launch, 4096 uniform blocks. Every block:
//   1. Front-issues ALL reads (8x x float4 + 2x mk float4, MLP=10) at
//      shift-independent addresses — the full 300MB read stream is in flight
//      chip-wide from cycle 0 (no moments prefix, no read-idle gating).
//   2. Reduces its mk slice (butterfly, fixed order) and commits associative
//      fixed-point atomics; the 128th arrival per batch finalizes (dx,dy)
//      (2 double divides per BATCH) and releases the batch flag.
//   3. Gates on its own batch's flag (commit precedes gate -> progress
//      cascades batch-by-batch; wave capacity ~740 >> 128 blocks/batch).
//   4. Scatter-stores out[h-dy, w-dx] = x[h,w] + zeros the disjoint border
//      complement (covers out exactly).
// ---------------------------------------------------------------------------
__global__ __launch_bounds__(256, 5)
void fused_kernel(const float4* __restrict__ x,
                  const float*  __restrict__ mk,
                  float4* __restrict__ out)
{
    const int bid   = blockIdx.x;
    const int b     = bid >> 7;               // batch
    const int chunk = bid & (CPB - 1);        // 0..127
    const int t     = threadIdx.x;
    const int lane  = t & 31;
    const int wid   = t >> 5;

    const float4* xb = x + ((size_t)b << 18);
    float4* ob       = out + ((size_t)b << 18);
    const int base   = chunk * (256 * SHIFT_ELEMS);   // pixel base in image

    // ---- 1. Front-issue ALL reads (shift-independent addresses) ----
    float4 v[SHIFT_ELEMS];
#pragma unroll
    for (int k = 0; k < SHIFT_ELEMS; k++)
        v[k] = xb[base + k * 256 + t];

    const float4* mbase =
        (const float4*)(mk + (size_t)b * PIX_PER_IMG) + chunk * MF4;
    const float4 m0 = mbase[t];
    const float4 m1 = mbase[t + 256];

    // ---- 2. Moments for this block's mk slice ----
    float s0 = 0.f, s1 = 0.f, s2 = 0.f;
#pragma unroll
    for (int i = 0; i < 2; i++) {
        const float4 m = (i == 0) ? m0 : m1;
        const int p = chunk * (MF4 * 4) + (t + i * 256) * 4;
        const int h = p >> 9;
        const int w = p & (W_ - 1);
        const float ry  = (float)(h - (H_ / 2));
        const float rx0 = (float)(w - (W_ / 2));
        const float sum = m.x + m.y + m.z + m.w;
        s0 += sum;
        s2 += ry * sum;
        s1 += rx0 * m.x + (rx0 + 1.f) * m.y + (rx0 + 2.f) * m.z
            + (rx0 + 3.f) * m.w;
    }

#pragma unroll
    for (int m = 16; m > 0; m >>= 1) {
        s0 += __shfl_xor_sync(0xffffffffu, s0, m);
        s1 += __shfl_xor_sync(0xffffffffu, s1, m);
        s2 += __shfl_xor_sync(0xffffffffu, s2, m);
    }

    __shared__ float w0[8], w1[8], w2[8];
    if (lane == 0) { w0[wid] = s0; w1[wid] = s1; w2[wid] = s2; }
    __syncthreads();

    if (t == 0) {
        float r0 = 0.f, r1 = 0.f, r2 = 0.f;
#pragma unroll
        for (int i = 0; i < 8; i++) { r0 += w0[i]; r1 += w1[i]; r2 += w2[i]; }
        atomicAdd((unsigned long long*)&g_tot[b * 3 + 0],
                  (unsigned long long)llrintf(r0 * FP_SCALE));
        atomicAdd((unsigned long long*)&g_tot[b * 3 + 1],
                  (unsigned long long)llrintf(r1 * FP_SCALE));
        atomicAdd((unsigned long long*)&g_tot[b * 3 + 2],
                  (unsigned long long)llrintf(r2 * FP_SCALE));
        __threadfence();

        if (atomicAdd(&g_cnt[b], 1u) == CPB - 1) {
            const long long t0v = (long long)atomicAdd(
                (unsigned long long*)&g_tot[b * 3 + 0], 0ull);
            const long long t1v = (long long)atomicAdd(
                (unsigned long long*)&g_tot[b * 3 + 1], 0ull);
            const long long t2v = (long long)atomicAdd(
                (unsigned long long*)&g_tot[b * 3 + 2], 0ull);
            const double den = fmax(1048.576, (double)t0v);  // 0.001*2^20
            // rint = round-half-even, matching jnp.round
            g_shift[b * 2 + 0] = (int)rint((double)t1v / den);   // dx
            g_shift[b * 2 + 1] = (int)rint((double)t2v / den);   // dy
            g_tot[b * 3 + 0] = 0ll;
            g_tot[b * 3 + 1] = 0ll;
            g_tot[b * 3 + 2] = 0ll;
            g_cnt[b] = 0u;
            __threadfence();                 // publish g_shift before flag
            atomicExch(&g_ready[b], 1u);
        }
    }

    // ---- 3. Gate (x loads remain in flight; commit already happened) ----
    __shared__ int s_dx, s_dy;
    if (t == 0) {
        while (atomicAdd(&g_ready[b], 0u) == 0u) __nanosleep(64);
        s_dx = atomicAdd(&((int*)g_shift)[b * 2 + 0], 0);
        s_dy = atomicAdd(&((int*)g_shift)[b * 2 + 1], 0);
    }
    __syncthreads();
    const int dx = s_dx;
    const int dy = s_dy;

    // ---- 4. Scatter-store + border zeroing ----
#pragma unroll
    for (int k = 0; k < SHIFT_ELEMS; k++) {
        const int p = base + k * 256 + t;    // source pixel (x coords)
        const int h = p >> 9;
        const int w = p & (W_ - 1);
        // Scatter: out[h-dy, w-dx] = x[h, w] when target in bounds.
        const int th = h - dy;
        const int tw = w - dx;
        if ((unsigned)th < (unsigned)H_ && (unsigned)tw < (unsigned)W_)
            ob[(th << 9) + tw] = v[k];
        // Border complement: out[p] = 0 when its source is out of bounds.
        const int sh = h + dy;
        const int sw = w + dx;
        if ((unsigned)sh >= (unsigned)H_ || (unsigned)sw >= (unsigned)W_)
            ob[p] = make_float4(0.f, 0.f, 0.f, 0.f);
    }

    // ---- Replay cleanup: last block overall resets the flags. Every block
    // has passed its gate before incrementing, so no one is stranded.
    __syncthreads();
    if (t == 0) {
        if (atomicAdd(&g_done, 1u) == GRID_TOTAL - 1) {
#pragma unroll
            for (int i = 0; i < B_; i++) g_ready[i] = 0u;
            g_done = 0u;
            __threadfence();
        }
    }
}

// ---------------------------------------------------------------------------
extern "C" void kernel_launch(void* const* d_in, const int* in_sizes, int n_in,
                              void* d_out, int out_size)
{
    const float* x  = (const float*)d_in[0];   // [32,512,512,4]
    const float* mk = (const float*)d_in[1];   // [32,512,512,1]

    fused_kernel<<<GRID_TOTAL, 256>>>((const float4*)x, mk, (float4*)d_out);
}